// round 3
// baseline (speedup 1.0000x reference)
#include <cuda_runtime.h>

// Slice geometry (fixed by the problem): H*W = 240*320 = 76800 elements per slice,
// B*K = 16*64 = 1024 slices. Derived defensively from in_sizes at launch.
#define HW        76800
#define HW4       (HW / 4)          // 19200 float4 per slice
#define MAX_SLICES 4096

// Scratch for per-slice variances (no cudaMalloc allowed).
__device__ float g_slice_var[MAX_SLICES];

__device__ __forceinline__ float warp_reduce_add(float v) {
    #pragma unroll
    for (int off = 16; off > 0; off >>= 1)
        v += __shfl_down_sync(0xFFFFFFFFu, v, off);
    return v;
}

// One CTA per slice: single-pass sum + sum-of-squares over 76800 floats.
__global__ __launch_bounds__(256, 8)
void slice_var_kernel(const float4* __restrict__ in, float* __restrict__ out_var) {
    const int slice = blockIdx.x;
    const float4* __restrict__ p = in + (size_t)slice * HW4;

    float s  = 0.0f;
    float sq = 0.0f;

    // 19200 float4 / 256 threads = 75 iterations; unroll for MLP (batched LDG.128).
    int i = threadIdx.x;
    #pragma unroll 5
    for (int it = 0; it < 75; ++it, i += 256) {
        float4 v = p[i];
        s  += (v.x + v.y) + (v.z + v.w);
        sq += v.x * v.x + v.y * v.y + v.z * v.z + v.w * v.w;
    }

    // Reduce within warp, then across the 8 warps via smem.
    s  = warp_reduce_add(s);
    sq = warp_reduce_add(sq);

    __shared__ float sm_s[8];
    __shared__ float sm_q[8];
    const int lane = threadIdx.x & 31;
    const int wid  = threadIdx.x >> 5;
    if (lane == 0) { sm_s[wid] = s; sm_q[wid] = sq; }
    __syncthreads();

    if (wid == 0) {
        float ts = (lane < 8) ? sm_s[lane] : 0.0f;
        float tq = (lane < 8) ? sm_q[lane] : 0.0f;
        ts = warp_reduce_add(ts);
        tq = warp_reduce_add(tq);
        if (lane == 0) {
            const float N = (float)HW;
            float var = (tq - ts * ts / N) / (N - 1.0f);
            out_var[slice] = var;
        }
    }
}

// Single CTA: sum n_slices variances, sqrt, write scalar.
__global__ __launch_bounds__(1024, 1)
void final_reduce_kernel(const float* __restrict__ var, float* __restrict__ out,
                         int n_slices) {
    float v = 0.0f;
    for (int i = threadIdx.x; i < n_slices; i += 1024)
        v += var[i];

    v = warp_reduce_add(v);

    __shared__ float sm[32];
    const int lane = threadIdx.x & 31;
    const int wid  = threadIdx.x >> 5;
    if (lane == 0) sm[wid] = v;
    __syncthreads();

    if (wid == 0) {
        float t = (lane < 32) ? sm[lane] : 0.0f;
        t = warp_reduce_add(t);
        if (lane == 0) out[0] = sqrtf(t);
    }
}

extern "C" void kernel_launch(void* const* d_in, const int* in_sizes, int n_in,
                              void* d_out, int out_size) {
    const float4* in = (const float4*)d_in[0];
    float* out = (float*)d_out;

    const int total   = in_sizes[0];
    const int n_slices = total / HW;   // 1024 for the given shape

    float* d_var;
    cudaGetSymbolAddress((void**)&d_var, g_slice_var);

    slice_var_kernel<<<n_slices, 256>>>(in, d_var);
    final_reduce_kernel<<<1, 1024>>>(d_var, out, n_slices);
}

// round 6
// speedup vs baseline: 1.0006x; 1.0006x over previous
#include <cuda_runtime.h>

// Slice geometry (fixed by the problem): H*W = 240*320 = 76800 elements/slice,
// B*K = 16*64 = 1024 slices. n_slices derived defensively from in_sizes.
#define HW        76800
#define HW4       (HW / 4)          // 19200 float4 per slice
#define MAX_SLICES 4096

// Scratch (no cudaMalloc allowed). Zero-initialized at module load; counter is
// self-resetting so every graph replay sees the same initial state.
__device__ float        g_slice_var[MAX_SLICES];
__device__ unsigned int g_counter;

__device__ __forceinline__ float warp_reduce_add(float v) {
    #pragma unroll
    for (int off = 16; off > 0; off >>= 1)
        v += __shfl_down_sync(0xFFFFFFFFu, v, off);
    return v;
}

// One CTA per slice: single-pass sum + sumsq over 76800 floats.
// Last CTA to finish also performs the cross-slice reduction + sqrt (fused,
// saves a 4.4us second launch).
__global__ __launch_bounds__(256, 8)
void loss_conc_kernel(const float4* __restrict__ in, float* __restrict__ out,
                      int n_slices) {
    const int slice = blockIdx.x;
    const float4* __restrict__ p = in + (size_t)slice * HW4;

    float s  = 0.0f;
    float sq = 0.0f;

    // 19200 float4 / 256 threads = 75 iterations; unroll 5 batches LDG.128 for MLP.
    int i = threadIdx.x;
    #pragma unroll 5
    for (int it = 0; it < 75; ++it, i += 256) {
        float4 v = p[i];
        s  += (v.x + v.y) + (v.z + v.w);
        sq += v.x * v.x + v.y * v.y + v.z * v.z + v.w * v.w;
    }

    s  = warp_reduce_add(s);
    sq = warp_reduce_add(sq);

    __shared__ float sm_s[8];
    __shared__ float sm_q[8];
    __shared__ bool  sm_last;
    const int lane = threadIdx.x & 31;
    const int wid  = threadIdx.x >> 5;
    if (lane == 0) { sm_s[wid] = s; sm_q[wid] = sq; }
    __syncthreads();

    if (wid == 0) {
        float ts = (lane < 8) ? sm_s[lane] : 0.0f;
        float tq = (lane < 8) ? sm_q[lane] : 0.0f;
        ts = warp_reduce_add(ts);
        tq = warp_reduce_add(tq);
        if (lane == 0) {
            const float N = (float)HW;
            g_slice_var[slice] = (tq - ts * ts / N) / (N - 1.0f);
            // Publish, then take a ticket. Last CTA sees all publishes.
            __threadfence();
            unsigned int ticket = atomicAdd(&g_counter, 1u);
            sm_last = (ticket == (unsigned int)gridDim.x - 1u);
        }
    }
    __syncthreads();

    if (sm_last) {
        if (threadIdx.x == 0) g_counter = 0;  // reset for next replay

        // Deterministic fixed-stride sum of slice variances (L2-hot).
        float v = 0.0f;
        for (int k = threadIdx.x; k < n_slices; k += 256)
            v += g_slice_var[k];
        v = warp_reduce_add(v);

        if (lane == 0) sm_s[wid] = v;
        __syncthreads();
        if (wid == 0) {
            float t = (lane < 8) ? sm_s[lane] : 0.0f;
            t = warp_reduce_add(t);
            if (lane == 0) out[0] = sqrtf(t);
        }
    }
}

extern "C" void kernel_launch(void* const* d_in, const int* in_sizes, int n_in,
                              void* d_out, int out_size) {
    const float4* in = (const float4*)d_in[0];
    float* out = (float*)d_out;

    const int total    = in_sizes[0];
    const int n_slices = total / HW;   // 1024 for the given shape

    loss_conc_kernel<<<n_slices, 256>>>(in, out, n_slices);
}